// round 2
// baseline (speedup 1.0000x reference)
#include <cuda_runtime.h>
#include <cuda_bf16.h>
#include <math.h>

#define NN 50000
#define EE 800000
#define KDIM 128
#define HID 128
#define CLS 40

// ---------------- scratch (device globals; no allocation allowed) ----------------
__device__ int   g_deg_out[NN];
__device__ int   g_deg_in[NN];
__device__ int   g_cursor[NN];
__device__ int   g_row_ptr[NN + 1];
__device__ int   g_col[EE];
__device__ float g_norm_out[NN];
__device__ float g_norm_in[NN];
__device__ float g_buf_a[(size_t)NN * 128];  // hW scratch (also used with stride 40 for layer 3)
__device__ float g_buf_h[(size_t)NN * 128];  // hidden activations

// ---------------- graph preprocessing ----------------
__global__ void init_zero_kernel(int n) {
    for (int i = blockIdx.x * blockDim.x + threadIdx.x; i < n; i += gridDim.x * blockDim.x) {
        g_deg_out[i] = 0;
        g_deg_in[i]  = 0;
        g_cursor[i]  = 0;
    }
}

__global__ void degree_kernel(const int* __restrict__ src, const int* __restrict__ dst, int E) {
    int e = blockIdx.x * blockDim.x + threadIdx.x;
    if (e < E) {
        atomicAdd(&g_deg_out[src[e]], 1);
        atomicAdd(&g_deg_in[dst[e]], 1);
    }
}

__global__ void norm_kernel(int n) {
    int i = blockIdx.x * blockDim.x + threadIdx.x;
    if (i < n) {
        int dout = g_deg_out[i]; if (dout < 1) dout = 1;
        int din  = g_deg_in[i];  if (din  < 1) din  = 1;
        g_norm_out[i] = rsqrtf((float)dout);
        g_norm_in[i]  = rsqrtf((float)din);
    }
}

// single-block exclusive scan of g_deg_in -> g_row_ptr (n up to ~1024*chunk)
__global__ void scan_kernel(int n) {
    __shared__ int s[1024];
    int tid = threadIdx.x;
    int chunk = (n + 1023) >> 10;
    int lo = tid * chunk;
    int hi = lo + chunk; if (hi > n) hi = n;
    int sum = 0;
    for (int i = lo; i < hi && i >= 0; ++i) sum += g_deg_in[i];
    s[tid] = sum;
    __syncthreads();
    // Hillis-Steele inclusive scan
    for (int off = 1; off < 1024; off <<= 1) {
        int v = (tid >= off) ? s[tid - off] : 0;
        __syncthreads();
        s[tid] += v;
        __syncthreads();
    }
    int run = (tid == 0) ? 0 : s[tid - 1];
    for (int i = lo; i < hi; ++i) {
        g_row_ptr[i] = run;
        run += g_deg_in[i];
    }
    if (hi == n) g_row_ptr[n] = run;  // all trailing threads write the same total
}

__global__ void csr_fill_kernel(const int* __restrict__ src, const int* __restrict__ dst, int E) {
    int e = blockIdx.x * blockDim.x + threadIdx.x;
    if (e < E) {
        int d = dst[e];
        int p = atomicAdd(&g_cursor[d], 1);
        g_col[g_row_ptr[d] + p] = src[e];
    }
}

// ---------------- GEMM: out[M x 128] = (A[M x 128] * norm_out[:,None]) @ W[128 x 128] ----------------
// BM=128, BN=128, BK=16, TM=TN=8, 256 threads
__global__ void __launch_bounds__(256)
gemm128_kernel(const float* __restrict__ A, const float* __restrict__ W,
               float* __restrict__ out, int M) {
    __shared__ float As[16][132];   // transposed A tile, padded
    __shared__ float Bs[16][128];

    int tid = threadIdx.x;
    int tx = tid & 15;         // col group (8 cols)
    int ty = tid >> 4;         // row group (8 rows)
    int rowBase = blockIdx.x * 128;

    int aRow = tid >> 2;             // 0..63
    int aCol = (tid & 3) << 2;       // 0,4,8,12
    int bRow = tid >> 5;             // 0..7
    int bCol = (tid & 31) << 2;      // 0..124

    float acc[8][8];
#pragma unroll
    for (int i = 0; i < 8; i++)
#pragma unroll
        for (int j = 0; j < 8; j++) acc[i][j] = 0.f;

    for (int kt = 0; kt < 128; kt += 16) {
        // load A tile (scaled by norm_out)
#pragma unroll
        for (int rr = 0; rr < 128; rr += 64) {
            int r = rowBase + aRow + rr;
            float4 v = make_float4(0.f, 0.f, 0.f, 0.f);
            if (r < M) {
                v = *(const float4*)(A + (size_t)r * 128 + kt + aCol);
                float s = g_norm_out[r];
                v.x *= s; v.y *= s; v.z *= s; v.w *= s;
            }
            As[aCol + 0][aRow + rr] = v.x;
            As[aCol + 1][aRow + rr] = v.y;
            As[aCol + 2][aRow + rr] = v.z;
            As[aCol + 3][aRow + rr] = v.w;
        }
        // load W tile
#pragma unroll
        for (int rr = 0; rr < 16; rr += 8) {
            float4 w = *(const float4*)(W + (size_t)(kt + bRow + rr) * 128 + bCol);
            *(float4*)(&Bs[bRow + rr][bCol]) = w;
        }
        __syncthreads();

#pragma unroll
        for (int k = 0; k < 16; k++) {
            float a[8], b[8];
            *(float4*)(a)     = *(const float4*)(&As[k][ty * 8]);
            *(float4*)(a + 4) = *(const float4*)(&As[k][ty * 8 + 4]);
            *(float4*)(b)     = *(const float4*)(&Bs[k][tx * 8]);
            *(float4*)(b + 4) = *(const float4*)(&Bs[k][tx * 8 + 4]);
#pragma unroll
            for (int i = 0; i < 8; i++)
#pragma unroll
                for (int j = 0; j < 8; j++)
                    acc[i][j] = fmaf(a[i], b[j], acc[i][j]);
        }
        __syncthreads();
    }

#pragma unroll
    for (int i = 0; i < 8; i++) {
        int r = rowBase + ty * 8 + i;
        if (r < M) {
            *(float4*)(out + (size_t)r * 128 + tx * 8)     = *(float4*)(&acc[i][0]);
            *(float4*)(out + (size_t)r * 128 + tx * 8 + 4) = *(float4*)(&acc[i][4]);
        }
    }
}

// ---------------- GEMM: out[M x 40] = (A[M x 128] * norm_out) @ W[128 x 40] ----------------
// BM=128, BN=64 (cols >= 40 padded with zeros), BK=16, TM=8, TN=4, 256 threads
__global__ void __launch_bounds__(256)
gemm40_kernel(const float* __restrict__ A, const float* __restrict__ W,
              float* __restrict__ out, int M) {
    __shared__ float As[16][132];
    __shared__ float Bs[16][64];

    int tid = threadIdx.x;
    int tx = tid & 15;          // col group (4 cols)
    int ty = tid >> 4;          // row group (8 rows)
    int rowBase = blockIdx.x * 128;

    int aRow = tid >> 2;
    int aCol = (tid & 3) << 2;
    int bRow = tid >> 4;        // 0..15
    int bCol = (tid & 15) << 2; // 0..60

    float acc[8][4];
#pragma unroll
    for (int i = 0; i < 8; i++)
#pragma unroll
        for (int j = 0; j < 4; j++) acc[i][j] = 0.f;

    for (int kt = 0; kt < 128; kt += 16) {
#pragma unroll
        for (int rr = 0; rr < 128; rr += 64) {
            int r = rowBase + aRow + rr;
            float4 v = make_float4(0.f, 0.f, 0.f, 0.f);
            if (r < M) {
                v = *(const float4*)(A + (size_t)r * 128 + kt + aCol);
                float s = g_norm_out[r];
                v.x *= s; v.y *= s; v.z *= s; v.w *= s;
            }
            As[aCol + 0][aRow + rr] = v.x;
            As[aCol + 1][aRow + rr] = v.y;
            As[aCol + 2][aRow + rr] = v.z;
            As[aCol + 3][aRow + rr] = v.w;
        }
        // W tile, scalar guarded (stride 40)
#pragma unroll
        for (int j = 0; j < 4; j++) {
            int c = bCol + j;
            Bs[bRow][bCol + j] = (c < CLS) ? W[(size_t)(kt + bRow) * CLS + c] : 0.f;
        }
        __syncthreads();

#pragma unroll
        for (int k = 0; k < 16; k++) {
            float a[8], b[4];
            *(float4*)(a)     = *(const float4*)(&As[k][ty * 8]);
            *(float4*)(a + 4) = *(const float4*)(&As[k][ty * 8 + 4]);
            *(float4*)(b)     = *(const float4*)(&Bs[k][tx * 4]);
#pragma unroll
            for (int i = 0; i < 8; i++)
#pragma unroll
                for (int j = 0; j < 4; j++)
                    acc[i][j] = fmaf(a[i], b[j], acc[i][j]);
        }
        __syncthreads();
    }

    if (tx * 4 < CLS) {  // CLS=40 is a multiple of 4, so whole float4 is in-bounds
#pragma unroll
        for (int i = 0; i < 8; i++) {
            int r = rowBase + ty * 8 + i;
            if (r < M)
                *(float4*)(out + (size_t)r * CLS + tx * 4) = *(float4*)(&acc[i][0]);
        }
    }
}

// ---------------- aggregation: out[d] = relu?( norm_in[d] * sum_{e in CSR[d]} tin[col[e]] + b ) ----------------
template <int C, int RELU>
__global__ void agg_kernel(const float* __restrict__ tin, const float* __restrict__ bias,
                           float* __restrict__ out) {
    int node = blockIdx.x;
    int c = threadIdx.x;
    if (c >= C) return;
    int beg = g_row_ptr[node];
    int end = g_row_ptr[node + 1];
    float acc = 0.f;
    int e = beg;
    for (; e + 1 < end; e += 2) {
        int s0 = g_col[e];
        int s1 = g_col[e + 1];
        float v0 = tin[(size_t)s0 * C + c];
        float v1 = tin[(size_t)s1 * C + c];
        acc += v0;
        acc += v1;
    }
    if (e < end) acc += tin[(size_t)g_col[e] * C + c];
    float v = acc * g_norm_in[node] + bias[c];
    if (RELU) v = fmaxf(v, 0.f);
    out[(size_t)node * C + c] = v;
}

// ---------------- host launcher ----------------
extern "C" void kernel_launch(void* const* d_in, const int* in_sizes, int n_in,
                              void* d_out, int out_size) {
    const float* features = (const float*)d_in[0];
    const int*   src      = (const int*)d_in[1];
    const int*   dst      = (const int*)d_in[2];
    const float* W0       = (const float*)d_in[3];
    const float* b0       = (const float*)d_in[4];
    const float* W1       = (const float*)d_in[5];
    const float* b1       = (const float*)d_in[6];
    const float* W2       = (const float*)d_in[7];
    const float* b2       = (const float*)d_in[8];
    float* out = (float*)d_out;

    int N = in_sizes[0] / KDIM;   // 50000
    int E = in_sizes[1];          // 800000

    float* p_buf_a = nullptr;
    float* p_buf_h = nullptr;
    cudaGetSymbolAddress((void**)&p_buf_a, g_buf_a);
    cudaGetSymbolAddress((void**)&p_buf_h, g_buf_h);

    // --- graph preprocessing ---
    init_zero_kernel<<<196, 256>>>(N);
    degree_kernel<<<(E + 255) / 256, 256>>>(src, dst, E);
    norm_kernel<<<(N + 255) / 256, 256>>>(N);
    scan_kernel<<<1, 1024>>>(N);
    csr_fill_kernel<<<(E + 255) / 256, 256>>>(src, dst, E);

    int gemmGrid = (N + 127) / 128;

    // --- layer 0: features -> h (relu) ---
    gemm128_kernel<<<gemmGrid, 256>>>(features, W0, p_buf_a, N);
    agg_kernel<HID, 1><<<N, 128>>>(p_buf_a, b0, p_buf_h);

    // --- layer 1: h -> h (relu) ---
    gemm128_kernel<<<gemmGrid, 256>>>(p_buf_h, W1, p_buf_a, N);
    agg_kernel<HID, 1><<<N, 128>>>(p_buf_a, b1, p_buf_h);

    // --- layer 2: h -> out (no relu, 40 classes) ---
    gemm40_kernel<<<gemmGrid, 256>>>(p_buf_h, W2, p_buf_a, N);
    agg_kernel<CLS, 0><<<N, 64>>>(p_buf_a, b2, out);
}

// round 3
// speedup vs baseline: 1.4005x; 1.4005x over previous
#include <cuda_runtime.h>
#include <cuda_bf16.h>
#include <math.h>
#include <stdint.h>

#define NN 50000
#define EE 800000
#define KDIM 128
#define HID 128
#define CLS 40

// ---------------- scratch (device globals; no allocation allowed) ----------------
__device__ int   g_deg_out[NN];
__device__ int   g_deg_in[NN];
__device__ int   g_cursor[NN];
__device__ int   g_row_ptr[NN + 1];
__device__ int   g_col[EE];
__device__ float g_norm_out[NN];
__device__ float g_norm_in[NN];
__device__ int   g_block_sums[256];
__device__ int   g_block_off[256];
__device__ float g_buf_a[(size_t)NN * 128];
__device__ float g_buf_h[(size_t)NN * 128];

// ---------------- graph preprocessing ----------------
__global__ void init_zero_kernel(int n) {
    for (int i = blockIdx.x * blockDim.x + threadIdx.x; i < n; i += gridDim.x * blockDim.x) {
        g_deg_out[i] = 0;
        g_deg_in[i]  = 0;
        g_cursor[i]  = 0;
    }
}

__global__ void degree_kernel(const int* __restrict__ src, const int* __restrict__ dst, int E) {
    int e = blockIdx.x * blockDim.x + threadIdx.x;
    if (e < E) {
        atomicAdd(&g_deg_out[src[e]], 1);
        atomicAdd(&g_deg_in[dst[e]], 1);
    }
}

__global__ void norm_kernel(int n) {
    int i = blockIdx.x * blockDim.x + threadIdx.x;
    if (i < n) {
        int dout = g_deg_out[i]; if (dout < 1) dout = 1;
        int din  = g_deg_in[i];  if (din  < 1) din  = 1;
        g_norm_out[i] = rsqrtf((float)dout);
        g_norm_in[i]  = rsqrtf((float)din);
    }
}

// --- parallel scan: per-block partial sums ---
__global__ void partial_sum_kernel(int n) {
    __shared__ int sdata[8];
    int t = threadIdx.x;
    int i = blockIdx.x * 256 + t;
    int v = (i < n) ? g_deg_in[i] : 0;
    // warp reduce
    for (int off = 16; off > 0; off >>= 1)
        v += __shfl_down_sync(0xffffffff, v, off);
    if ((t & 31) == 0) sdata[t >> 5] = v;
    __syncthreads();
    if (t < 8) {
        int w = sdata[t];
        for (int off = 4; off > 0; off >>= 1)
            w += __shfl_down_sync(0xff, w, off);
        if (t == 0) g_block_sums[blockIdx.x] = w;
    }
}

// --- scan of block sums (nblocks <= 256) ---
__global__ void scan_offsets_kernel(int nblocks, int n) {
    __shared__ int s[256];
    int t = threadIdx.x;
    int v = (t < nblocks) ? g_block_sums[t] : 0;
    s[t] = v;
    __syncthreads();
    for (int off = 1; off < 256; off <<= 1) {
        int u = (t >= off) ? s[t - off] : 0;
        __syncthreads();
        s[t] += u;
        __syncthreads();
    }
    if (t < nblocks) g_block_off[t] = s[t] - v;      // exclusive
    if (t == nblocks - 1) g_row_ptr[n] = s[t];       // total = E
}

// --- fill row_ptr with block-local exclusive scan + offset ---
__global__ void fill_rowptr_kernel(int n) {
    __shared__ int s[256];
    int t = threadIdx.x;
    int i = blockIdx.x * 256 + t;
    int v = (i < n) ? g_deg_in[i] : 0;
    s[t] = v;
    __syncthreads();
    for (int off = 1; off < 256; off <<= 1) {
        int u = (t >= off) ? s[t - off] : 0;
        __syncthreads();
        s[t] += u;
        __syncthreads();
    }
    if (i < n) g_row_ptr[i] = s[t] - v + g_block_off[blockIdx.x];
}

__global__ void csr_fill_kernel(const int* __restrict__ src, const int* __restrict__ dst, int E) {
    int e = blockIdx.x * blockDim.x + threadIdx.x;
    if (e < E) {
        int d = dst[e];
        int p = atomicAdd(&g_cursor[d], 1);
        g_col[g_row_ptr[d] + p] = src[e];
    }
}

// ---------------- TF32 tensor-core GEMM: out[M x 128] = A[M x 128] @ W[128 x 128] ----------------
// Block: 128 rows x 128 cols, 8 warps (2x4), warp tile 64x32. Whole K=128 in smem.
// As padded to 132 words/row, Ws padded to 136 words/row (conflict-free frag loads).
#define APAD 132
#define WPAD 136
#define GEMM_SMEM_BYTES ((128 * APAD + 128 * WPAD) * 4)

__device__ __forceinline__ uint32_t f2tf32(float f) {
    uint32_t u;
    asm volatile("cvt.rna.tf32.f32 %0, %1;" : "=r"(u) : "f"(f));
    return u;
}

__global__ void __launch_bounds__(256)
gemm_tf32_kernel(const float* __restrict__ A, const float* __restrict__ W,
                 float* __restrict__ out, int M) {
    extern __shared__ uint32_t sm[];
    uint32_t* As = sm;                 // [128][APAD]
    uint32_t* Ws = sm + 128 * APAD;    // [128][WPAD]

    int tid  = threadIdx.x;
    int warp = tid >> 5;
    int lane = tid & 31;
    int rowBase = blockIdx.x * 128;

    // ---- load + convert A tile (128x128 floats = 4096 float4, 16/thread) ----
#pragma unroll
    for (int it = 0; it < 16; it++) {
        int li = it * 256 + tid;
        int r  = li >> 5;              // 0..127
        int c4 = (li & 31) << 2;       // 0..124 step 4
        float4 v = make_float4(0.f, 0.f, 0.f, 0.f);
        if (rowBase + r < M)
            v = *(const float4*)(A + (size_t)(rowBase + r) * 128 + c4);
        uint32_t* p = As + r * APAD + c4;
        p[0] = f2tf32(v.x); p[1] = f2tf32(v.y); p[2] = f2tf32(v.z); p[3] = f2tf32(v.w);
    }
    // ---- load + convert W tile (K x N row-major, 128x128) ----
#pragma unroll
    for (int it = 0; it < 16; it++) {
        int li = it * 256 + tid;
        int k  = li >> 5;
        int n4 = (li & 31) << 2;
        float4 v = *(const float4*)(W + (size_t)k * 128 + n4);
        uint32_t* p = Ws + k * WPAD + n4;
        p[0] = f2tf32(v.x); p[1] = f2tf32(v.y); p[2] = f2tf32(v.z); p[3] = f2tf32(v.w);
    }
    __syncthreads();

    int warpRow = warp >> 2;           // 0..1  -> 64-row slab
    int warpCol = warp & 3;            // 0..3  -> 32-col slab
    int groupID = lane >> 2;           // 0..7
    int tig     = lane & 3;            // 0..3
    int aRowBase = warpRow * 64;
    int bColBase = warpCol * 32;

    float acc[4][4][4];
#pragma unroll
    for (int mf = 0; mf < 4; mf++)
#pragma unroll
        for (int nf = 0; nf < 4; nf++)
#pragma unroll
            for (int q = 0; q < 4; q++) acc[mf][nf][q] = 0.f;

#pragma unroll
    for (int ks = 0; ks < 128; ks += 8) {
        uint32_t bfr[4][2];
#pragma unroll
        for (int nf = 0; nf < 4; nf++) {
            int n = bColBase + nf * 8 + groupID;
            bfr[nf][0] = Ws[(ks + tig)     * WPAD + n];
            bfr[nf][1] = Ws[(ks + tig + 4) * WPAD + n];
        }
        uint32_t afr[4][4];
#pragma unroll
        for (int mf = 0; mf < 4; mf++) {
            int r = aRowBase + mf * 16 + groupID;
            afr[mf][0] = As[r       * APAD + ks + tig];
            afr[mf][1] = As[(r + 8) * APAD + ks + tig];
            afr[mf][2] = As[r       * APAD + ks + tig + 4];
            afr[mf][3] = As[(r + 8) * APAD + ks + tig + 4];
        }
#pragma unroll
        for (int mf = 0; mf < 4; mf++)
#pragma unroll
            for (int nf = 0; nf < 4; nf++) {
                asm volatile(
                    "mma.sync.aligned.m16n8k8.row.col.f32.tf32.tf32.f32 "
                    "{%0,%1,%2,%3}, {%4,%5,%6,%7}, {%8,%9}, {%0,%1,%2,%3};"
                    : "+f"(acc[mf][nf][0]), "+f"(acc[mf][nf][1]),
                      "+f"(acc[mf][nf][2]), "+f"(acc[mf][nf][3])
                    : "r"(afr[mf][0]), "r"(afr[mf][1]), "r"(afr[mf][2]), "r"(afr[mf][3]),
                      "r"(bfr[nf][0]), "r"(bfr[nf][1]));
            }
    }

    // ---- epilogue ----
#pragma unroll
    for (int mf = 0; mf < 4; mf++) {
        int r0 = rowBase + aRowBase + mf * 16 + groupID;
        int r1 = r0 + 8;
#pragma unroll
        for (int nf = 0; nf < 4; nf++) {
            int col = bColBase + nf * 8 + tig * 2;
            if (r0 < M)
                *(float2*)(out + (size_t)r0 * 128 + col) =
                    make_float2(acc[mf][nf][0], acc[mf][nf][1]);
            if (r1 < M)
                *(float2*)(out + (size_t)r1 * 128 + col) =
                    make_float2(acc[mf][nf][2], acc[mf][nf][3]);
        }
    }
}

// ---------------- GEMM: out[M x 40] = A[M x 128] @ W[128 x 40] (SIMT fp32) ----------------
__global__ void __launch_bounds__(256)
gemm40_kernel(const float* __restrict__ A, const float* __restrict__ W,
              float* __restrict__ out, int M) {
    __shared__ float As[16][132];
    __shared__ float Bs[16][64];

    int tid = threadIdx.x;
    int tx = tid & 15;
    int ty = tid >> 4;
    int rowBase = blockIdx.x * 128;

    int aRow = tid >> 2;
    int aCol = (tid & 3) << 2;
    int bRow = tid >> 4;
    int bCol = (tid & 15) << 2;

    float acc[8][4];
#pragma unroll
    for (int i = 0; i < 8; i++)
#pragma unroll
        for (int j = 0; j < 4; j++) acc[i][j] = 0.f;

    for (int kt = 0; kt < 128; kt += 16) {
#pragma unroll
        for (int rr = 0; rr < 128; rr += 64) {
            int r = rowBase + aRow + rr;
            float4 v = make_float4(0.f, 0.f, 0.f, 0.f);
            if (r < M)
                v = *(const float4*)(A + (size_t)r * 128 + kt + aCol);
            As[aCol + 0][aRow + rr] = v.x;
            As[aCol + 1][aRow + rr] = v.y;
            As[aCol + 2][aRow + rr] = v.z;
            As[aCol + 3][aRow + rr] = v.w;
        }
#pragma unroll
        for (int j = 0; j < 4; j++) {
            int c = bCol + j;
            Bs[bRow][bCol + j] = (c < CLS) ? W[(size_t)(kt + bRow) * CLS + c] : 0.f;
        }
        __syncthreads();

#pragma unroll
        for (int k = 0; k < 16; k++) {
            float a[8], b[4];
            *(float4*)(a)     = *(const float4*)(&As[k][ty * 8]);
            *(float4*)(a + 4) = *(const float4*)(&As[k][ty * 8 + 4]);
            *(float4*)(b)     = *(const float4*)(&Bs[k][tx * 4]);
#pragma unroll
            for (int i = 0; i < 8; i++)
#pragma unroll
                for (int j = 0; j < 4; j++)
                    acc[i][j] = fmaf(a[i], b[j], acc[i][j]);
        }
        __syncthreads();
    }

    if (tx * 4 < CLS) {
#pragma unroll
        for (int i = 0; i < 8; i++) {
            int r = rowBase + ty * 8 + i;
            if (r < M)
                *(float4*)(out + (size_t)r * CLS + tx * 4) = *(float4*)(&acc[i][0]);
        }
    }
}

// ---------------- aggregation ----------------
// EW: per-edge weight norm_out[src] (used when GEMM input was NOT pre-scaled)
// OS: epilogue multiply by norm_out[dst] (pre-scales input of the NEXT layer's GEMM)
template <int C, int RELU, int EW, int OS>
__global__ void agg_kernel(const float* __restrict__ tin, const float* __restrict__ bias,
                           float* __restrict__ out) {
    int node = blockIdx.x;
    int c = threadIdx.x;
    if (c >= C) return;
    int beg = g_row_ptr[node];
    int end = g_row_ptr[node + 1];
    float acc = 0.f;
    int e = beg;
    for (; e + 1 < end; e += 2) {
        int s0 = g_col[e];
        int s1 = g_col[e + 1];
        float v0 = tin[(size_t)s0 * C + c];
        float v1 = tin[(size_t)s1 * C + c];
        if (EW) {
            acc = fmaf(v0, g_norm_out[s0], acc);
            acc = fmaf(v1, g_norm_out[s1], acc);
        } else {
            acc += v0;
            acc += v1;
        }
    }
    if (e < end) {
        int s0 = g_col[e];
        float v0 = tin[(size_t)s0 * C + c];
        if (EW) acc = fmaf(v0, g_norm_out[s0], acc);
        else    acc += v0;
    }
    float v = acc * g_norm_in[node] + bias[c];
    if (RELU) v = fmaxf(v, 0.f);
    if (OS)   v *= g_norm_out[node];
    out[(size_t)node * C + c] = v;
}

// ---------------- host launcher ----------------
extern "C" void kernel_launch(void* const* d_in, const int* in_sizes, int n_in,
                              void* d_out, int out_size) {
    const float* features = (const float*)d_in[0];
    const int*   src      = (const int*)d_in[1];
    const int*   dst      = (const int*)d_in[2];
    const float* W0       = (const float*)d_in[3];
    const float* b0       = (const float*)d_in[4];
    const float* W1       = (const float*)d_in[5];
    const float* b1       = (const float*)d_in[6];
    const float* W2       = (const float*)d_in[7];
    const float* b2       = (const float*)d_in[8];
    float* out = (float*)d_out;

    int N = in_sizes[0] / KDIM;   // 50000
    int E = in_sizes[1];          // 800000

    static cudaStream_t s_pre = nullptr;
    static cudaEvent_t  ev_fork = nullptr, ev_join = nullptr;
    static float* p_buf_a = nullptr;
    static float* p_buf_h = nullptr;
    if (!s_pre) {
        cudaStreamCreateWithFlags(&s_pre, cudaStreamNonBlocking);
        cudaEventCreateWithFlags(&ev_fork, cudaEventDisableTiming);
        cudaEventCreateWithFlags(&ev_join, cudaEventDisableTiming);
        cudaGetSymbolAddress((void**)&p_buf_a, g_buf_a);
        cudaGetSymbolAddress((void**)&p_buf_h, g_buf_h);
        cudaFuncSetAttribute(gemm_tf32_kernel,
                             cudaFuncAttributeMaxDynamicSharedMemorySize,
                             GEMM_SMEM_BYTES);
    }

    int nScanBlocks = (N + 255) / 256;
    int gemmGrid = (N + 127) / 128;

    // ---- fork: preprocessing on s_pre, GEMM0 (graph-independent) on main ----
    cudaEventRecord(ev_fork, 0);
    cudaStreamWaitEvent(s_pre, ev_fork, 0);

    init_zero_kernel<<<196, 256, 0, s_pre>>>(N);
    degree_kernel<<<(E + 255) / 256, 256, 0, s_pre>>>(src, dst, E);
    norm_kernel<<<(N + 255) / 256, 256, 0, s_pre>>>(N);
    partial_sum_kernel<<<nScanBlocks, 256, 0, s_pre>>>(N);
    scan_offsets_kernel<<<1, 256, 0, s_pre>>>(nScanBlocks, N);
    fill_rowptr_kernel<<<nScanBlocks, 256, 0, s_pre>>>(N);
    csr_fill_kernel<<<(E + 255) / 256, 256, 0, s_pre>>>(src, dst, E);
    cudaEventRecord(ev_join, s_pre);

    // layer 0 GEMM: plain (norm_out applied per-edge in agg0)
    gemm_tf32_kernel<<<gemmGrid, 256, GEMM_SMEM_BYTES>>>(features, W0, p_buf_a, N);

    cudaStreamWaitEvent(0, ev_join, 0);

    // ---- layer 0 agg: edge-weighted, relu, pre-scale for next gemm ----
    agg_kernel<HID, 1, 1, 1><<<N, 128>>>(p_buf_a, b0, p_buf_h);

    // ---- layer 1 ----
    gemm_tf32_kernel<<<gemmGrid, 256, GEMM_SMEM_BYTES>>>(p_buf_h, W1, p_buf_a, N);
    agg_kernel<HID, 1, 0, 1><<<N, 128>>>(p_buf_a, b1, p_buf_h);

    // ---- layer 2 (40 classes) ----
    gemm40_kernel<<<gemmGrid, 256>>>(p_buf_h, W2, p_buf_a, N);
    agg_kernel<CLS, 0, 0, 0><<<N, 64>>>(p_buf_a, b2, out);
}

// round 4
// speedup vs baseline: 1.9002x; 1.3568x over previous
#include <cuda_runtime.h>
#include <cuda_fp16.h>
#include <math.h>
#include <stdint.h>

#define NN 50000
#define EE 800000
#define KDIM 128
#define HID 128
#define CLS 40

// ---------------- scratch (device globals; no allocation allowed) ----------------
__device__ int   g_deg_out[NN];
__device__ int   g_deg_in[NN];
__device__ int   g_cursor[NN];
__device__ int   g_row_ptr[NN + 1];
__device__ int   g_col[EE];
__device__ float g_norm_out[NN];
__device__ float g_norm_in[NN];
__device__ int   g_block_sums[256];
__device__ int   g_block_off[256];
__device__ float g_buf_a[(size_t)NN * 128];   // fp16 hW scratch (as __half2) / fp32 stride-40 for layer 3
__device__ float g_buf_h[(size_t)NN * 128];   // fp32 hidden activations

// ---------------- graph preprocessing ----------------
__global__ void init_zero_kernel(int n) {
    for (int i = blockIdx.x * blockDim.x + threadIdx.x; i < n; i += gridDim.x * blockDim.x) {
        g_deg_out[i] = 0;
        g_deg_in[i]  = 0;
        g_cursor[i]  = 0;
    }
}

__global__ void degree_kernel(const int* __restrict__ src, const int* __restrict__ dst, int E) {
    int e = blockIdx.x * blockDim.x + threadIdx.x;
    if (e < E) {
        atomicAdd(&g_deg_out[src[e]], 1);
        atomicAdd(&g_deg_in[dst[e]], 1);
    }
}

__global__ void norm_kernel(int n) {
    int i = blockIdx.x * blockDim.x + threadIdx.x;
    if (i < n) {
        int dout = g_deg_out[i]; if (dout < 1) dout = 1;
        int din  = g_deg_in[i];  if (din  < 1) din  = 1;
        g_norm_out[i] = rsqrtf((float)dout);
        g_norm_in[i]  = rsqrtf((float)din);
    }
}

__global__ void partial_sum_kernel(int n) {
    __shared__ int sdata[8];
    int t = threadIdx.x;
    int i = blockIdx.x * 256 + t;
    int v = (i < n) ? g_deg_in[i] : 0;
    for (int off = 16; off > 0; off >>= 1)
        v += __shfl_down_sync(0xffffffff, v, off);
    if ((t & 31) == 0) sdata[t >> 5] = v;
    __syncthreads();
    if (t < 8) {
        int w = sdata[t];
        for (int off = 4; off > 0; off >>= 1)
            w += __shfl_down_sync(0xff, w, off);
        if (t == 0) g_block_sums[blockIdx.x] = w;
    }
}

__global__ void scan_offsets_kernel(int nblocks, int n) {
    __shared__ int s[256];
    int t = threadIdx.x;
    int v = (t < nblocks) ? g_block_sums[t] : 0;
    s[t] = v;
    __syncthreads();
    for (int off = 1; off < 256; off <<= 1) {
        int u = (t >= off) ? s[t - off] : 0;
        __syncthreads();
        s[t] += u;
        __syncthreads();
    }
    if (t < nblocks) g_block_off[t] = s[t] - v;
    if (t == nblocks - 1) g_row_ptr[n] = s[t];
}

__global__ void fill_rowptr_kernel(int n) {
    __shared__ int s[256];
    int t = threadIdx.x;
    int i = blockIdx.x * 256 + t;
    int v = (i < n) ? g_deg_in[i] : 0;
    s[t] = v;
    __syncthreads();
    for (int off = 1; off < 256; off <<= 1) {
        int u = (t >= off) ? s[t - off] : 0;
        __syncthreads();
        s[t] += u;
        __syncthreads();
    }
    if (i < n) g_row_ptr[i] = s[t] - v + g_block_off[blockIdx.x];
}

__global__ void csr_fill_kernel(const int* __restrict__ src, const int* __restrict__ dst, int E) {
    int e = blockIdx.x * blockDim.x + threadIdx.x;
    if (e < E) {
        int d = dst[e];
        int p = atomicAdd(&g_cursor[d], 1);
        g_col[g_row_ptr[d] + p] = src[e];
    }
}

// ---------------- TF32 tensor-core GEMM (128 cols, fp16 output) ----------------
#define APAD 132
#define WPAD 136
#define GEMM_SMEM_BYTES ((128 * APAD + 128 * WPAD) * 4)

__device__ __forceinline__ uint32_t f2tf32(float f) {
    uint32_t u;
    asm volatile("cvt.rna.tf32.f32 %0, %1;" : "=r"(u) : "f"(f));
    return u;
}

__global__ void __launch_bounds__(256)
gemm_tf32_kernel(const float* __restrict__ A, const float* __restrict__ W,
                 __half2* __restrict__ out, int M) {
    extern __shared__ uint32_t sm[];
    uint32_t* As = sm;                 // [128][APAD]
    uint32_t* Ws = sm + 128 * APAD;    // [128][WPAD]

    int tid  = threadIdx.x;
    int warp = tid >> 5;
    int lane = tid & 31;
    int rowBase = blockIdx.x * 128;

#pragma unroll
    for (int it = 0; it < 16; it++) {
        int li = it * 256 + tid;
        int r  = li >> 5;
        int c4 = (li & 31) << 2;
        float4 v = make_float4(0.f, 0.f, 0.f, 0.f);
        if (rowBase + r < M)
            v = *(const float4*)(A + (size_t)(rowBase + r) * 128 + c4);
        uint32_t* p = As + r * APAD + c4;
        p[0] = f2tf32(v.x); p[1] = f2tf32(v.y); p[2] = f2tf32(v.z); p[3] = f2tf32(v.w);
    }
#pragma unroll
    for (int it = 0; it < 16; it++) {
        int li = it * 256 + tid;
        int k  = li >> 5;
        int n4 = (li & 31) << 2;
        float4 v = *(const float4*)(W + (size_t)k * 128 + n4);
        uint32_t* p = Ws + k * WPAD + n4;
        p[0] = f2tf32(v.x); p[1] = f2tf32(v.y); p[2] = f2tf32(v.z); p[3] = f2tf32(v.w);
    }
    __syncthreads();

    int warpRow = warp >> 2;
    int warpCol = warp & 3;
    int groupID = lane >> 2;
    int tig     = lane & 3;
    int aRowBase = warpRow * 64;
    int bColBase = warpCol * 32;

    float acc[4][4][4];
#pragma unroll
    for (int mf = 0; mf < 4; mf++)
#pragma unroll
        for (int nf = 0; nf < 4; nf++)
#pragma unroll
            for (int q = 0; q < 4; q++) acc[mf][nf][q] = 0.f;

#pragma unroll
    for (int ks = 0; ks < 128; ks += 8) {
        uint32_t bfr[4][2];
#pragma unroll
        for (int nf = 0; nf < 4; nf++) {
            int n = bColBase + nf * 8 + groupID;
            bfr[nf][0] = Ws[(ks + tig)     * WPAD + n];
            bfr[nf][1] = Ws[(ks + tig + 4) * WPAD + n];
        }
        uint32_t afr[4][4];
#pragma unroll
        for (int mf = 0; mf < 4; mf++) {
            int r = aRowBase + mf * 16 + groupID;
            afr[mf][0] = As[r       * APAD + ks + tig];
            afr[mf][1] = As[(r + 8) * APAD + ks + tig];
            afr[mf][2] = As[r       * APAD + ks + tig + 4];
            afr[mf][3] = As[(r + 8) * APAD + ks + tig + 4];
        }
#pragma unroll
        for (int mf = 0; mf < 4; mf++)
#pragma unroll
            for (int nf = 0; nf < 4; nf++) {
                asm volatile(
                    "mma.sync.aligned.m16n8k8.row.col.f32.tf32.tf32.f32 "
                    "{%0,%1,%2,%3}, {%4,%5,%6,%7}, {%8,%9}, {%0,%1,%2,%3};"
                    : "+f"(acc[mf][nf][0]), "+f"(acc[mf][nf][1]),
                      "+f"(acc[mf][nf][2]), "+f"(acc[mf][nf][3])
                    : "r"(afr[mf][0]), "r"(afr[mf][1]), "r"(afr[mf][2]), "r"(afr[mf][3]),
                      "r"(bfr[nf][0]), "r"(bfr[nf][1]));
            }
    }

    // epilogue: convert to half2, write (64 half2 words per row)
#pragma unroll
    for (int mf = 0; mf < 4; mf++) {
        int r0 = rowBase + aRowBase + mf * 16 + groupID;
        int r1 = r0 + 8;
#pragma unroll
        for (int nf = 0; nf < 4; nf++) {
            int h2col = ((bColBase + nf * 8) >> 1) + tig;
            if (r0 < M)
                out[(size_t)r0 * 64 + h2col] =
                    __float22half2_rn(make_float2(acc[mf][nf][0], acc[mf][nf][1]));
            if (r1 < M)
                out[(size_t)r1 * 64 + h2col] =
                    __float22half2_rn(make_float2(acc[mf][nf][2], acc[mf][nf][3]));
        }
    }
}

// ---------------- TF32 tensor-core GEMM: out[M x 40] = A[M x 128] @ W[128 x 40] (fp32 out) ----------------
#define W2PAD 40
#define GEMM40_SMEM_BYTES ((128 * APAD + 128 * W2PAD) * 4)

__global__ void __launch_bounds__(256)
gemm40_tf32_kernel(const float* __restrict__ A, const float* __restrict__ W,
                   float* __restrict__ out, int M) {
    extern __shared__ uint32_t sm[];
    uint32_t* As = sm;                 // [128][APAD]
    uint32_t* Ws = sm + 128 * APAD;    // [128][W2PAD]

    int tid  = threadIdx.x;
    int warp = tid >> 5;
    int lane = tid & 31;
    int rowBase = blockIdx.x * 128;

#pragma unroll
    for (int it = 0; it < 16; it++) {
        int li = it * 256 + tid;
        int r  = li >> 5;
        int c4 = (li & 31) << 2;
        float4 v = make_float4(0.f, 0.f, 0.f, 0.f);
        if (rowBase + r < M)
            v = *(const float4*)(A + (size_t)(rowBase + r) * 128 + c4);
        uint32_t* p = As + r * APAD + c4;
        p[0] = f2tf32(v.x); p[1] = f2tf32(v.y); p[2] = f2tf32(v.z); p[3] = f2tf32(v.w);
    }
    // W2: 128 x 40 = 1280 float4
#pragma unroll
    for (int it = 0; it < 5; it++) {
        int li = it * 256 + tid;
        int k  = li / 10;
        int n4 = (li % 10) << 2;
        float4 v = *(const float4*)(W + (size_t)k * CLS + n4);
        uint32_t* p = Ws + k * W2PAD + n4;
        p[0] = f2tf32(v.x); p[1] = f2tf32(v.y); p[2] = f2tf32(v.z); p[3] = f2tf32(v.w);
    }
    __syncthreads();

    int groupID = lane >> 2;
    int tig     = lane & 3;
    int aRowBase = warp * 16;          // each warp owns 16 rows x 40 cols

    float acc[5][4];
#pragma unroll
    for (int nf = 0; nf < 5; nf++)
#pragma unroll
        for (int q = 0; q < 4; q++) acc[nf][q] = 0.f;

#pragma unroll
    for (int ks = 0; ks < 128; ks += 8) {
        uint32_t afr[4];
        {
            int r = aRowBase + groupID;
            afr[0] = As[r       * APAD + ks + tig];
            afr[1] = As[(r + 8) * APAD + ks + tig];
            afr[2] = As[r       * APAD + ks + tig + 4];
            afr[3] = As[(r + 8) * APAD + ks + tig + 4];
        }
#pragma unroll
        for (int nf = 0; nf < 5; nf++) {
            int n = nf * 8 + groupID;
            uint32_t b0 = Ws[(ks + tig)     * W2PAD + n];
            uint32_t b1 = Ws[(ks + tig + 4) * W2PAD + n];
            asm volatile(
                "mma.sync.aligned.m16n8k8.row.col.f32.tf32.tf32.f32 "
                "{%0,%1,%2,%3}, {%4,%5,%6,%7}, {%8,%9}, {%0,%1,%2,%3};"
                : "+f"(acc[nf][0]), "+f"(acc[nf][1]), "+f"(acc[nf][2]), "+f"(acc[nf][3])
                : "r"(afr[0]), "r"(afr[1]), "r"(afr[2]), "r"(afr[3]),
                  "r"(b0), "r"(b1));
        }
    }

    int r0 = rowBase + aRowBase + groupID;
    int r1 = r0 + 8;
#pragma unroll
    for (int nf = 0; nf < 5; nf++) {
        int col = nf * 8 + tig * 2;
        if (r0 < M)
            *(float2*)(out + (size_t)r0 * CLS + col) = make_float2(acc[nf][0], acc[nf][1]);
        if (r1 < M)
            *(float2*)(out + (size_t)r1 * CLS + col) = make_float2(acc[nf][2], acc[nf][3]);
    }
}

// ---------------- aggregation over fp16 gather operand (128 cols) ----------------
// EW: per-edge weight norm_out[src]; OS: epilogue multiply by norm_out[dst]
template <int RELU, int EW, int OS>
__global__ void __launch_bounds__(256)
agg_f16_kernel(const __half2* __restrict__ tin, const float* __restrict__ bias,
               float* __restrict__ out, int N) {
    int node = blockIdx.x * blockDim.y + threadIdx.y;
    if (node >= N) return;
    int c = threadIdx.x;               // 0..63 (half2 word index)
    int beg = g_row_ptr[node];
    int end = g_row_ptr[node + 1];
    float ax = 0.f, ay = 0.f;
    int e = beg;
    for (; e + 3 < end; e += 4) {
        int s0 = g_col[e], s1 = g_col[e + 1], s2 = g_col[e + 2], s3 = g_col[e + 3];
        float2 f0 = __half22float2(tin[(size_t)s0 * 64 + c]);
        float2 f1 = __half22float2(tin[(size_t)s1 * 64 + c]);
        float2 f2 = __half22float2(tin[(size_t)s2 * 64 + c]);
        float2 f3 = __half22float2(tin[(size_t)s3 * 64 + c]);
        if (EW) {
            float w0 = g_norm_out[s0], w1 = g_norm_out[s1];
            float w2 = g_norm_out[s2], w3 = g_norm_out[s3];
            ax = fmaf(f0.x, w0, ax); ay = fmaf(f0.y, w0, ay);
            ax = fmaf(f1.x, w1, ax); ay = fmaf(f1.y, w1, ay);
            ax = fmaf(f2.x, w2, ax); ay = fmaf(f2.y, w2, ay);
            ax = fmaf(f3.x, w3, ax); ay = fmaf(f3.y, w3, ay);
        } else {
            ax += f0.x + f1.x + f2.x + f3.x;
            ay += f0.y + f1.y + f2.y + f3.y;
        }
    }
    for (; e < end; e++) {
        int s0 = g_col[e];
        float2 f0 = __half22float2(tin[(size_t)s0 * 64 + c]);
        if (EW) {
            float w0 = g_norm_out[s0];
            ax = fmaf(f0.x, w0, ax); ay = fmaf(f0.y, w0, ay);
        } else {
            ax += f0.x; ay += f0.y;
        }
    }
    float ni = g_norm_in[node];
    float vx = ax * ni + bias[2 * c];
    float vy = ay * ni + bias[2 * c + 1];
    if (RELU) { vx = fmaxf(vx, 0.f); vy = fmaxf(vy, 0.f); }
    if (OS)   { float s = g_norm_out[node]; vx *= s; vy *= s; }
    *(float2*)(out + (size_t)node * 128 + 2 * c) = make_float2(vx, vy);
}

// ---------------- aggregation fp32 (40 cols, final layer) ----------------
__global__ void agg40_kernel(const float* __restrict__ tin, const float* __restrict__ bias,
                             float* __restrict__ out, int N) {
    int node = blockIdx.x * blockDim.y + threadIdx.y;
    if (node >= N) return;
    int c = threadIdx.x;               // 0..39
    if (c >= CLS) return;
    int beg = g_row_ptr[node];
    int end = g_row_ptr[node + 1];
    float acc = 0.f;
    int e = beg;
    for (; e + 1 < end; e += 2) {
        float v0 = tin[(size_t)g_col[e]     * CLS + c];
        float v1 = tin[(size_t)g_col[e + 1] * CLS + c];
        acc += v0;
        acc += v1;
    }
    if (e < end) acc += tin[(size_t)g_col[e] * CLS + c];
    out[(size_t)node * CLS + c] = acc * g_norm_in[node] + bias[c];
}

// ---------------- host launcher ----------------
extern "C" void kernel_launch(void* const* d_in, const int* in_sizes, int n_in,
                              void* d_out, int out_size) {
    const float* features = (const float*)d_in[0];
    const int*   src      = (const int*)d_in[1];
    const int*   dst      = (const int*)d_in[2];
    const float* W0       = (const float*)d_in[3];
    const float* b0       = (const float*)d_in[4];
    const float* W1       = (const float*)d_in[5];
    const float* b1       = (const float*)d_in[6];
    const float* W2       = (const float*)d_in[7];
    const float* b2       = (const float*)d_in[8];
    float* out = (float*)d_out;

    int N = in_sizes[0] / KDIM;   // 50000
    int E = in_sizes[1];          // 800000

    static cudaStream_t s_pre = nullptr;
    static cudaEvent_t  ev_fork = nullptr, ev_join = nullptr;
    static float* p_buf_a = nullptr;
    static float* p_buf_h = nullptr;
    if (!s_pre) {
        cudaStreamCreateWithFlags(&s_pre, cudaStreamNonBlocking);
        cudaEventCreateWithFlags(&ev_fork, cudaEventDisableTiming);
        cudaEventCreateWithFlags(&ev_join, cudaEventDisableTiming);
        cudaGetSymbolAddress((void**)&p_buf_a, g_buf_a);
        cudaGetSymbolAddress((void**)&p_buf_h, g_buf_h);
        cudaFuncSetAttribute(gemm_tf32_kernel,
                             cudaFuncAttributeMaxDynamicSharedMemorySize,
                             GEMM_SMEM_BYTES);
        cudaFuncSetAttribute(gemm40_tf32_kernel,
                             cudaFuncAttributeMaxDynamicSharedMemorySize,
                             GEMM40_SMEM_BYTES);
    }

    __half2* buf16 = (__half2*)p_buf_a;

    int nScanBlocks = (N + 255) / 256;
    int gemmGrid = (N + 127) / 128;
    int aggGrid = (N + 3) / 4;

    // ---- fork: preprocessing on s_pre, GEMM0 (graph-independent) on main ----
    cudaEventRecord(ev_fork, 0);
    cudaStreamWaitEvent(s_pre, ev_fork, 0);

    init_zero_kernel<<<196, 256, 0, s_pre>>>(N);
    degree_kernel<<<(E + 255) / 256, 256, 0, s_pre>>>(src, dst, E);
    norm_kernel<<<(N + 255) / 256, 256, 0, s_pre>>>(N);
    partial_sum_kernel<<<nScanBlocks, 256, 0, s_pre>>>(N);
    scan_offsets_kernel<<<1, 256, 0, s_pre>>>(nScanBlocks, N);
    fill_rowptr_kernel<<<nScanBlocks, 256, 0, s_pre>>>(N);
    csr_fill_kernel<<<(E + 255) / 256, 256, 0, s_pre>>>(src, dst, E);
    cudaEventRecord(ev_join, s_pre);

    // layer 0 GEMM: plain (norm_out applied per-edge in agg0)
    gemm_tf32_kernel<<<gemmGrid, 256, GEMM_SMEM_BYTES>>>(features, W0, buf16, N);

    cudaStreamWaitEvent(0, ev_join, 0);

    // layer 0 agg: edge-weighted, relu, pre-scale for next gemm
    agg_f16_kernel<1, 1, 1><<<aggGrid, dim3(64, 4)>>>(buf16, b0, p_buf_h, N);

    // layer 1
    gemm_tf32_kernel<<<gemmGrid, 256, GEMM_SMEM_BYTES>>>(p_buf_h, W1, buf16, N);
    agg_f16_kernel<1, 0, 1><<<aggGrid, dim3(64, 4)>>>(buf16, b1, p_buf_h, N);

    // layer 2 (40 classes, fp32 path)
    gemm40_tf32_kernel<<<gemmGrid, 256, GEMM40_SMEM_BYTES>>>(p_buf_h, W2, p_buf_a, N);
    agg40_kernel<<<(N + 5) / 6, dim3(40, 6)>>>(p_buf_a, b2, out, N);
}